// round 16
// baseline (speedup 1.0000x reference)
#include <cuda_runtime.h>
#include <cstdint>
#include <cstddef>

// Problem constants
#define Gc 64
#define NODESc 511
#define Nc 512          // NODES + 1 (graph token at row 0 of each graph)
#define Hc 768
#define Ec 4096
#define Mc (Gc * Nc)    // 32768 rows
#define NT 5            // distinct source vectors: node_emb[0..3], graph_emb (t=4)
#define RPB 16          // rows per writer block (all roles)

// Row split: kernelA writes out1 for rows [0, SPLIT); kernelB does the rest.
#define SPLIT 6656                    // = 416 * 16
#define NBLK_CNT  Gc                  // 64 counting blocks
#define NBLK_PROJ 256                 // 256 * 6 warps = 1536 proj tasks
#define NPROD (NBLK_CNT + NBLK_PROJ)  // 320
#define NBLK_W_A (SPLIT / RPB)        // 416 out1 writer blocks in kernelA
#define NBLK_FUSED ((Mc - SPLIT) / RPB)  // 1632 fused out1+out2 blocks in kernelB
#define NBLK_O2 (SPLIT / RPB)         // 416 out2-only blocks in kernelB

// Scratch (device globals; allocation is forbidden)
__device__ int   g_cnt[Mc * NT];     // per-dst-row counts of source types
__device__ float g_Q[NT * Hc];       // emb5 @ W_l^T
__device__ float g_Pb[NT * Hc];      // emb5 @ W_r^T + b_l  (bias folded in)

// ---------------------------------------------------------------------------
// Kernel A, blockDim = 192. Producers first, then a small out1 writer slab
// (just enough store work to hide the producers):
//   bid [0, 64):          per-graph edge counting in shared memory
//   bid [64, 320):        Q/Pb projection, 6 warps/block, warp per (matrix,col)
//   bid [320, 320+416):   out1 writer for rows [0, SPLIT), 16 rows/block
// ---------------------------------------------------------------------------
__global__ __launch_bounds__(192) void kernelA(
    const int* __restrict__ nodes,
    const int* __restrict__ edges,
    const float* __restrict__ node_emb,
    const float* __restrict__ graph_emb,
    const float* __restrict__ Wl,
    const float* __restrict__ Wr,
    const float* __restrict__ bl,
    float* __restrict__ out1) {
    const int tid = threadIdx.x;

    if (blockIdx.x < NBLK_CNT) {
        // ---- per-graph counting ----
        __shared__ int scnt[Nc * NT];    // 10 KB
        __shared__ int stype[Nc];
        const int g = blockIdx.x;

        #pragma unroll
        for (int i = tid; i < Nc * NT; i += 192) scnt[i] = 0;
        if (tid == 0) stype[0] = 4;
        for (int i = tid; i < NODESc; i += 192)
            stype[i + 1] = __ldg(nodes + g * NODESc + i);
        __syncthreads();

        const int* eg = edges + (size_t)g * 2 * Ec;
        #pragma unroll
        for (int e = tid; e < Ec; e += 192) {
            int src = __ldg(eg + e);
            int dst = __ldg(eg + Ec + e);
            atomicAdd(&scnt[dst * NT + stype[src]], 1);
        }
        __syncthreads();

        int4* dst4 = reinterpret_cast<int4*>(g_cnt + (size_t)g * Nc * NT);
        const int4* src4 = reinterpret_cast<const int4*>(scnt);
        #pragma unroll
        for (int i = tid; i < (Nc * NT) / 4; i += 192)
            dst4[i] = src4[i];
        return;
    }

    if (blockIdx.x < NPROD) {
        // ---- Q/Pb projection: warp w -> (matrix = w&1, column n = w>>1) ----
        const int wglob = (blockIdx.x - NBLK_CNT) * 6 + (tid >> 5);   // 0..1535
        const int lane  = tid & 31;
        const int mtx   = wglob & 1;        // 0: Wl -> Q, 1: Wr -> Pb
        const int n     = wglob >> 1;       // 0..767

        const float4* Wrow = reinterpret_cast<const float4*>((mtx ? Wr : Wl) + (size_t)n * Hc);
        const float4* e4[NT];
        #pragma unroll
        for (int t = 0; t < 4; ++t)
            e4[t] = reinterpret_cast<const float4*>(node_emb + (size_t)t * Hc);
        e4[4] = reinterpret_cast<const float4*>(graph_emb);

        float acc[NT] = {0.f, 0.f, 0.f, 0.f, 0.f};
        #pragma unroll
        for (int k4 = lane; k4 < Hc / 4; k4 += 32) {
            float4 wv = Wrow[k4];
            #pragma unroll
            for (int t = 0; t < NT; ++t) {
                float4 ev = e4[t][k4];
                acc[t] = fmaf(ev.x, wv.x,
                         fmaf(ev.y, wv.y,
                         fmaf(ev.z, wv.z,
                         fmaf(ev.w, wv.w, acc[t]))));
            }
        }
        #pragma unroll
        for (int t = 0; t < NT; ++t)
            #pragma unroll
            for (int off = 16; off; off >>= 1)
                acc[t] += __shfl_xor_sync(0xffffffffu, acc[t], off);

        if (lane == 0) {
            float* dst = mtx ? g_Pb : g_Q;
            float badd = mtx ? __ldg(bl + n) : 0.f;
            #pragma unroll
            for (int t = 0; t < NT; ++t)
                dst[t * Hc + n] = acc[t] + badd;
        }
        return;
    }

    // ---- out1 writer: rows [0, SPLIT), out1[row] = emb5[type(row)] ----
    __shared__ float4 sEb[NT][192];
    __shared__ int    sT[RPB];
    const int n4 = tid;
    const int row0 = (blockIdx.x - NPROD) * RPB;

    #pragma unroll
    for (int t = 0; t < 4; ++t)
        sEb[t][n4] = reinterpret_cast<const float4*>(node_emb + (size_t)t * Hc)[n4];
    sEb[4][n4] = reinterpret_cast<const float4*>(graph_emb)[n4];
    if (n4 < RPB) {
        int row = row0 + n4;
        int g = row >> 9;
        int i = row & 511;
        sT[n4] = (i == 0) ? 4 : __ldg(nodes + g * NODESc + i - 1);
    }
    __syncthreads();

    float4* o1p = reinterpret_cast<float4*>(out1 + (size_t)row0 * Hc) + n4;
    #pragma unroll
    for (int r = 0; r < RPB; ++r) {
        __stcs(o1p, sEb[sT[r]][n4]);
        o1p += Hc / 4;
    }
}

// ---------------------------------------------------------------------------
// Kernel B, blockDim = 192:
//   bid [0, 1632):       fused out1+out2 writer for rows [SPLIT, Mc)
//                        (the measured-5.9TB/s two-stream loop from R12)
//   bid [1632, 2048):    out2-only writer for rows [0, SPLIT)
// out2[m][n] = sum_t (cnt[m][t]/deg) * Q[t][n] + Pb[type(m)][n]
// ---------------------------------------------------------------------------
__global__ __launch_bounds__(192) void kernelB(
    const int* __restrict__ nodes,
    const float* __restrict__ node_emb,
    const float* __restrict__ graph_emb,
    float* __restrict__ out1,
    float* __restrict__ out2) {
    __shared__ float4 sEb[NT][192];      // 15 KB (fused role only)
    __shared__ float4 sPb[NT][192];      // 15 KB
    __shared__ float  sC[RPB][NT];
    __shared__ int    sT[RPB];

    const int n4 = threadIdx.x;
    const bool fused = blockIdx.x < NBLK_FUSED;
    const int row0 = fused ? SPLIT + blockIdx.x * RPB
                           : (blockIdx.x - NBLK_FUSED) * RPB;

    // Stage tables
    #pragma unroll
    for (int t = 0; t < NT; ++t)
        sPb[t][n4] = reinterpret_cast<const float4*>(g_Pb + (size_t)t * Hc)[n4];
    if (fused) {
        #pragma unroll
        for (int t = 0; t < 4; ++t)
            sEb[t][n4] = reinterpret_cast<const float4*>(node_emb + (size_t)t * Hc)[n4];
        sEb[4][n4] = reinterpret_cast<const float4*>(graph_emb)[n4];
    }

    float4 Q[NT];
    #pragma unroll
    for (int t = 0; t < NT; ++t)
        Q[t] = reinterpret_cast<const float4*>(g_Q + (size_t)t * Hc)[n4];

    if (n4 < RPB) {
        int row = row0 + n4;
        int g = row >> 9;
        int i = row & 511;
        sT[n4] = (i == 0) ? 4 : __ldg(nodes + g * NODESc + i - 1);
        const int* cp = g_cnt + (size_t)row * NT;
        float c[NT];
        float deg = 0.f;
        #pragma unroll
        for (int t = 0; t < NT; ++t) { c[t] = (float)__ldg(cp + t); deg += c[t]; }
        float inv = 1.0f / fmaxf(deg, 1.0f);
        #pragma unroll
        for (int t = 0; t < NT; ++t) sC[n4][t] = c[t] * inv;
    }
    __syncthreads();

    float4* o1p = reinterpret_cast<float4*>(out1 + (size_t)row0 * Hc) + n4;
    float4* o2p = reinterpret_cast<float4*>(out2 + (size_t)row0 * Hc) + n4;

    if (fused) {
        #pragma unroll
        for (int r = 0; r < RPB; ++r) {
            int trow = sT[r];
            float c0 = sC[r][0], c1 = sC[r][1], c2 = sC[r][2], c3 = sC[r][3], c4 = sC[r][4];
            float4 o1 = sEb[trow][n4];
            float4 o2 = sPb[trow][n4];
            o2.x = fmaf(c0, Q[0].x, fmaf(c1, Q[1].x, fmaf(c2, Q[2].x, fmaf(c3, Q[3].x, fmaf(c4, Q[4].x, o2.x)))));
            o2.y = fmaf(c0, Q[0].y, fmaf(c1, Q[1].y, fmaf(c2, Q[2].y, fmaf(c3, Q[3].y, fmaf(c4, Q[4].y, o2.y)))));
            o2.z = fmaf(c0, Q[0].z, fmaf(c1, Q[1].z, fmaf(c2, Q[2].z, fmaf(c3, Q[3].z, fmaf(c4, Q[4].z, o2.z)))));
            o2.w = fmaf(c0, Q[0].w, fmaf(c1, Q[1].w, fmaf(c2, Q[2].w, fmaf(c3, Q[3].w, fmaf(c4, Q[4].w, o2.w)))));
            __stcs(o1p, o1);
            __stcs(o2p, o2);
            o1p += Hc / 4;
            o2p += Hc / 4;
        }
    } else {
        #pragma unroll
        for (int r = 0; r < RPB; ++r) {
            float c0 = sC[r][0], c1 = sC[r][1], c2 = sC[r][2], c3 = sC[r][3], c4 = sC[r][4];
            float4 o2 = sPb[sT[r]][n4];
            o2.x = fmaf(c0, Q[0].x, fmaf(c1, Q[1].x, fmaf(c2, Q[2].x, fmaf(c3, Q[3].x, fmaf(c4, Q[4].x, o2.x)))));
            o2.y = fmaf(c0, Q[0].y, fmaf(c1, Q[1].y, fmaf(c2, Q[2].y, fmaf(c3, Q[3].y, fmaf(c4, Q[4].y, o2.y)))));
            o2.z = fmaf(c0, Q[0].z, fmaf(c1, Q[1].z, fmaf(c2, Q[2].z, fmaf(c3, Q[3].z, fmaf(c4, Q[4].z, o2.z)))));
            o2.w = fmaf(c0, Q[0].w, fmaf(c1, Q[1].w, fmaf(c2, Q[2].w, fmaf(c3, Q[3].w, fmaf(c4, Q[4].w, o2.w)))));
            __stcs(o2p, o2);
            o2p += Hc / 4;
        }
    }
}

// ---------------------------------------------------------------------------
// Launch. Inputs: input_nodes(i32), input_edges(i32), node_emb(f32),
//                 graph_emb(f32), W_l(f32), b_l(f32), W_r(f32)
// d_out: [graph_node_feature | graph_edge_feature]
// ---------------------------------------------------------------------------
extern "C" void kernel_launch(void* const* d_in, const int* in_sizes, int n_in,
                              void* d_out, int out_size) {
    const int*   nodes     = (const int*)d_in[0];
    const int*   edges     = (const int*)d_in[1];
    const float* node_emb  = (const float*)d_in[2];
    const float* graph_emb = (const float*)d_in[3];
    const float* Wl        = (const float*)d_in[4];
    const float* bl        = (const float*)d_in[5];
    const float* Wr        = (const float*)d_in[6];

    float* out1 = (float*)d_out;
    float* out2 = out1 + (size_t)Mc * Hc;

    kernelA<<<NPROD + NBLK_W_A, 192>>>(nodes, edges, node_emb, graph_emb,
                                       Wl, Wr, bl, out1);
    kernelB<<<NBLK_FUSED + NBLK_O2, 192>>>(nodes, node_emb, graph_emb, out1, out2);
}